// round 6
// baseline (speedup 1.0000x reference)
#include <cuda_runtime.h>
#include <cstdint>

// ---------------- problem constants ----------------
#define NTOK 8192
#define DDIM 4096
#define NEXP 64
#define CAP  160
#define EC   (NEXP * CAP)                 // 10240
#define DISP_OFF  ((size_t)0)
#define COMB_OFF  ((size_t)NTOK * EC)                  // 83,886,080
#define PROBS_OFF ((size_t)2 * NTOK * EC)              // 167,772,160
#define LOSS_OFF  (PROBS_OFF + (size_t)NTOK * NEXP)    // 168,296,448

#define KSPLIT 4
#define KC     (DDIM / KSPLIT)            // 1024
#define KSTAGE 16
#define NSTAGE (KC / KSTAGE)              // 64
#define TOKTILE 128
#define NTILE  (NTOK / TOKTILE)           // 64
#define GEMM_BLOCKS (NTILE * KSPLIT)      // 256
#define ATPB 256                          // 128 GEMM threads + 128 store threads
#define TPB  256

// zero-fill geometry: 128 store threads per block * 256 blocks
#define ZTHREADS (GEMM_BLOCKS * 128)              // 32768
#define TOTAL4   (PROBS_OFF / 4)                  // 41,943,040 float4
#define ZITERS   (TOTAL4 / ZTHREADS)              // 1280 exactly

// ---------------- scratch ----------------
__device__ float g_part[KSPLIT][NTOK][NEXP];   // 8 MB partial logits
__device__ int   g_top_e[NTOK * 2];
__device__ float g_top_v[NTOK * 2];
__device__ float g_floss[NEXP];
__device__ int   g_cnt[NTILE];                 // per-tile k-split arrival (self-resetting)
__device__ int   g_done;                       // slots-kernel arrival (self-resetting)

__device__ __forceinline__ unsigned long long dup64(float v) {
    unsigned long long r;
    asm("mov.b64 %0, {%1, %1};" : "=l"(r) : "f"(v));
    return r;
}
__device__ __forceinline__ void bar_gemm() {
    asm volatile("bar.sync 1, 128;" ::: "memory");
}

// ============================================================================
// Kernel A: warp-specialized [zero-fill] + [k-split GEMM] + [fused softmax].
// 256 blocks x 256 threads. Warps 0-3: GEMM (named barrier). Warps 4-7:
// streaming zero-fill of dispatch+combine. The last k-split block per token
// tile reduces partials and does softmax/top-2 (fixed order => deterministic).
// ============================================================================
__global__ __launch_bounds__(ATPB) void router_kernel(
    const float* __restrict__ x,   // (NTOK, DDIM)
    const float* __restrict__ w,   // (NEXP, DDIM)
    float* __restrict__ out)
{
    const int tid = threadIdx.x;

    __shared__ __align__(16) float xs[2][KSTAGE][TOKTILE];   // 16 KB
    __shared__ __align__(16) float ws[2][KSTAGE][68];        // 8.5 KB
    __shared__ int s_last;

    // ---------------- store half: zero-fill ----------------
    if (tid >= 128) {
        float4* o4 = reinterpret_cast<float4*>(out);
        const float4 z = make_float4(0.f, 0.f, 0.f, 0.f);
        unsigned i = (unsigned)blockIdx.x * 128u + (unsigned)(tid - 128);
        const unsigned stride = ZTHREADS;
#pragma unroll 4
        for (int it = 0; it < ZITERS; ++it) {
            __stcs(o4 + i, z);
            i += stride;
        }
        return;
    }

    // ---------------- GEMM half: 128 tok x 64 exp x 1024 k ----------------
    const int split = blockIdx.x & (KSPLIT - 1);
    const int tile  = blockIdx.x >> 2;
    const int tok0  = tile * TOKTILE;
    const int ks    = split * KC;

    const int ex = tid & 7;  const int e0 = ex * 8;
    const int ty = tid >> 3; const int t0 = ty * 8;
    const int e0p = e0 + ((e0 >> 5) << 2);   // bank-swizzled w column

    const float* xg = x + (size_t)(tok0 + tid) * DDIM + ks;   // token row = tid
    const int we = tid & 63; const int wh = (tid >> 6) & 1;   // expert, k-half
    const float* wg = w + (size_t)we * DDIM + ks + wh * 8;
    const int wep = we + ((we >> 5) << 2);

    unsigned long long acc[4][8];
#pragma unroll
    for (int i = 0; i < 4; i++)
#pragma unroll
        for (int j = 0; j < 8; j++) acc[i][j] = 0ull;

    float4 xr[4], wr[2];

    // prologue: stage 0
#pragma unroll
    for (int j = 0; j < 4; j++) xr[j] = __ldcs((const float4*)(xg + j * 4));
#pragma unroll
    for (int j = 0; j < 2; j++) wr[j] = *(const float4*)(wg + j * 4);
#pragma unroll
    for (int j = 0; j < 4; j++) {
        xs[0][j * 4 + 0][tid] = xr[j].x; xs[0][j * 4 + 1][tid] = xr[j].y;
        xs[0][j * 4 + 2][tid] = xr[j].z; xs[0][j * 4 + 3][tid] = xr[j].w;
    }
#pragma unroll
    for (int j = 0; j < 2; j++) {
        const int kb = wh * 8 + j * 4;
        ws[0][kb + 0][wep] = wr[j].x; ws[0][kb + 1][wep] = wr[j].y;
        ws[0][kb + 2][wep] = wr[j].z; ws[0][kb + 3][wep] = wr[j].w;
    }
    bar_gemm();

    for (int s = 0; s < NSTAGE; s++) {
        const int b = s & 1;
        if (s + 1 < NSTAGE) {
            const int ko = (s + 1) * KSTAGE;
#pragma unroll
            for (int j = 0; j < 4; j++)
                xr[j] = __ldcs((const float4*)(xg + ko + j * 4));
#pragma unroll
            for (int j = 0; j < 2; j++)
                wr[j] = *(const float4*)(wg + ko + j * 4);
        }

#pragma unroll
        for (int k = 0; k < KSTAGE; k++) {
            const ulonglong2 A01 = *(const ulonglong2*)&xs[b][k][t0];
            const ulonglong2 A23 = *(const ulonglong2*)&xs[b][k][t0 + 4];
            const float4 w0 = *(const float4*)&ws[b][k][e0p];
            const float4 w1 = *(const float4*)&ws[b][k][e0p + 4];
            unsigned long long bd[8];
            bd[0] = dup64(w0.x); bd[1] = dup64(w0.y);
            bd[2] = dup64(w0.z); bd[3] = dup64(w0.w);
            bd[4] = dup64(w1.x); bd[5] = dup64(w1.y);
            bd[6] = dup64(w1.z); bd[7] = dup64(w1.w);
            const unsigned long long A[4] = {A01.x, A01.y, A23.x, A23.y};
#pragma unroll
            for (int tp = 0; tp < 4; tp++)
#pragma unroll
                for (int e = 0; e < 8; e++)
                    asm("fma.rn.f32x2 %0, %1, %2, %0;"
                        : "+l"(acc[tp][e]) : "l"(A[tp]), "l"(bd[e]));
        }

        bar_gemm();
        if (s + 1 < NSTAGE) {
            const int nb = (s + 1) & 1;
#pragma unroll
            for (int j = 0; j < 4; j++) {
                xs[nb][j * 4 + 0][tid] = xr[j].x; xs[nb][j * 4 + 1][tid] = xr[j].y;
                xs[nb][j * 4 + 2][tid] = xr[j].z; xs[nb][j * 4 + 3][tid] = xr[j].w;
            }
#pragma unroll
            for (int j = 0; j < 2; j++) {
                const int kb = wh * 8 + j * 4;
                ws[nb][kb + 0][wep] = wr[j].x; ws[nb][kb + 1][wep] = wr[j].y;
                ws[nb][kb + 2][wep] = wr[j].z; ws[nb][kb + 3][wep] = wr[j].w;
            }
            bar_gemm();
        }
    }

    // epilogue: write partial logits
#pragma unroll
    for (int tp = 0; tp < 4; tp++) {
        const int tok = tok0 + t0 + 2 * tp;
        float* p0 = &g_part[split][tok][e0];
        float* p1 = &g_part[split][tok + 1][e0];
#pragma unroll
        for (int e = 0; e < 8; e++) {
            unsigned lo, hi;
            asm("mov.b64 {%0, %1}, %2;" : "=r"(lo), "=r"(hi) : "l"(acc[tp][e]));
            p0[e] = __uint_as_float(lo);
            p1[e] = __uint_as_float(hi);
        }
    }

    // ---------------- fused k-split reduce + softmax + top-2 ----------------
    __threadfence();            // release g_part
    bar_gemm();
    if (tid == 0) s_last = (atomicAdd(&g_cnt[tile], 1) == KSPLIT - 1) ? 1 : 0;
    bar_gemm();
    if (!s_last) return;
    __threadfence();            // acquire other splits' g_part

    const int lane = tid & 31;
    const int warp = tid >> 5;
    for (int t8 = 0; t8 < 32; t8++) {
        const int tok = tok0 + warp * 32 + t8;
        float v0 = 0.f, v1 = 0.f;
#pragma unroll
        for (int s = 0; s < KSPLIT; s++) {
            v0 += g_part[s][tok][lane];
            v1 += g_part[s][tok][lane + 32];
        }
        const int i0 = lane, i1 = lane + 32;

        float b1v, b2v; int b1i, b2i;
        if (v0 >= v1) { b1v = v0; b1i = i0; b2v = v1; b2i = i1; }
        else          { b1v = v1; b1i = i1; b2v = v0; b2i = i0; }
#pragma unroll
        for (int off = 16; off; off >>= 1) {
            const float o1v = __shfl_xor_sync(0xffffffffu, b1v, off);
            const int   o1i = __shfl_xor_sync(0xffffffffu, b1i, off);
            const float o2v = __shfl_xor_sync(0xffffffffu, b2v, off);
            const int   o2i = __shfl_xor_sync(0xffffffffu, b2i, off);
            const bool o1_better = (o1v > b1v) || (o1v == b1v && o1i < b1i);
            if (o1_better) {
                const bool b1_vs_o2 = (b1v > o2v) || (b1v == o2v && b1i < o2i);
                b2v = b1_vs_o2 ? b1v : o2v;
                b2i = b1_vs_o2 ? b1i : o2i;
                b1v = o1v; b1i = o1i;
            } else {
                const bool o1_vs_b2 = (o1v > b2v) || (o1v == b2v && o1i < b2i);
                if (o1_vs_b2) { b2v = o1v; b2i = o1i; }
            }
        }

        const float m = b1v;
        const float p0 = expf(v0 - m);
        const float p1 = expf(v1 - m);
        float ssum = p0 + p1;
#pragma unroll
        for (int off = 16; off; off >>= 1)
            ssum += __shfl_xor_sync(0xffffffffu, ssum, off);
        const float inv = 1.0f / ssum;

        out[PROBS_OFF + (size_t)tok * NEXP + lane]      = p0 * inv;
        out[PROBS_OFF + (size_t)tok * NEXP + lane + 32] = p1 * inv;

        if (lane == 0) {
            const float e2 = expf(b2v - b1v);
            const float wn = 1.0f / (1.0f + e2);   // normalized top-1 weight
            g_top_e[2 * tok]     = b1i;
            g_top_e[2 * tok + 1] = b2i;
            g_top_v[2 * tok]     = wn;
            g_top_v[2 * tok + 1] = e2 * wn;
        }
    }
    if (tid == 0) g_cnt[tile] = 0;   // self-reset for graph replay
}

// ============================================================================
// Kernel B: one block per expert. Ordered exclusive prefix over the flattened
// assignment stream, scatter nonzeros inline, probs column mean, fused loss.
// ============================================================================
__global__ __launch_bounds__(TPB) void slots_kernel(float* __restrict__ out)
{
    const int e = blockIdx.x;
    const int tid = threadIdx.x;
    const int lane = tid & 31;
    const int warp = tid >> 5;

    __shared__ int wcnt[8];
    int base = 0;
    for (int i0 = 0; i0 < NTOK * 2; i0 += TPB) {
        const int i = i0 + tid;
        const int flag = (g_top_e[i] == e) ? 1 : 0;
        const unsigned m = __ballot_sync(0xffffffffu, flag);
        if (lane == 0) wcnt[warp] = __popc(m);
        __syncthreads();
        int woff = 0, tot = 0;
#pragma unroll
        for (int ww = 0; ww < 8; ww++) {
            const int c = wcnt[ww];
            if (ww < warp) woff += c;
            tot += c;
        }
        if (flag) {
            const int slot = base + woff + __popc(m & ((1u << lane) - 1u));
            if (slot < CAP) {
                const int tok = i >> 1;
                const size_t idx = (size_t)tok * EC + (size_t)e * CAP + slot;
                out[DISP_OFF + idx] = 1.0f;
                out[COMB_OFF + idx] = g_top_v[i];
            }
        }
        base += tot;
        __syncthreads();
    }

    // probs column-e sum (deterministic fixed-order tree)
    float ps = 0.f;
    const float* probs = out + PROBS_OFF;
    for (int n = tid; n < NTOK; n += TPB) ps += probs[(size_t)n * NEXP + e];
    __shared__ float red[TPB];
    red[tid] = ps;
    __syncthreads();
    for (int s = TPB / 2; s; s >>= 1) {
        if (tid < s) red[tid] += red[tid + s];
        __syncthreads();
    }
    if (tid == 0) {
        g_floss[e] = ((float)base * (1.0f / (NTOK * 2))) * (red[0] * (1.0f / NTOK));
        __threadfence();
        if (atomicAdd(&g_done, 1) == NEXP - 1) {
            __threadfence();
            float ssum = 0.f;
            for (int ee = 0; ee < NEXP; ee++) ssum += g_floss[ee];
            out[LOSS_OFF] = 0.01f * (float)NEXP * ssum;
            g_done = 0;                      // self-reset for graph replay
        }
    }
}

// ============================================================================
extern "C" void kernel_launch(void* const* d_in, const int* in_sizes, int n_in,
                              void* d_out, int out_size)
{
    (void)in_sizes; (void)n_in; (void)out_size;
    const float* x = (const float*)d_in[0];
    const float* w = (const float*)d_in[1];
    float* out = (float*)d_out;

    router_kernel<<<GEMM_BLOCKS, ATPB>>>(x, w, out);
    slots_kernel<<<NEXP, TPB>>>(out);
}

// round 9
// speedup vs baseline: 1.1804x; 1.1804x over previous
#include <cuda_runtime.h>
#include <cstdint>

// ---------------- problem constants ----------------
#define NTOK 8192
#define DDIM 4096
#define NEXP 64
#define CAP  160
#define EC   (NEXP * CAP)                 // 10240
#define DISP_OFF  ((size_t)0)
#define COMB_OFF  ((size_t)NTOK * EC)                  // 83,886,080
#define PROBS_OFF ((size_t)2 * NTOK * EC)              // 167,772,160
#define LOSS_OFF  (PROBS_OFF + (size_t)NTOK * NEXP)    // 168,296,448

#define KSPLIT 8
#define KC     (DDIM / KSPLIT)            // 512
#define KSTAGE 16
#define NSTAGE (KC / KSTAGE)              // 32
#define TOKTILE 128
#define NTILE  (NTOK / TOKTILE)           // 64
#define GEMM_BLOCKS (NTILE * KSPLIT)      // 512
#define ZERO_BLOCKS 1024
#define GRID (GEMM_BLOCKS + ZERO_BLOCKS)  // 1536
#define ATPB 128
#define TPB  256

// zero-fill geometry
#define ZTHREADS (ZERO_BLOCKS * ATPB)             // 131072
#define TOTAL4   (PROBS_OFF / 4)                  // 41,943,040 float4
#define ZITERS   (TOTAL4 / ZTHREADS)              // 320 exactly

// ---------------- scratch ----------------
__device__ float g_part[KSPLIT][NTOK][NEXP];   // 16 MB partial logits
__device__ int   g_top_e[NTOK * 2];
__device__ float g_top_v[NTOK * 2];
__device__ int   g_slot [NTOK * 2];
__device__ float g_floss[NEXP];

__device__ __forceinline__ unsigned long long dup64(float v) {
    unsigned long long r;
    asm("mov.b64 %0, {%1, %1};" : "=l"(r) : "f"(v));
    return r;
}

// ============================================================================
// Kernel A: fused [zero-fill] + [k-split GEMM], interleaved block mapping
// (every 3rd block is a GEMM block) so both populations spread across SMs.
// 512 GEMM blocks (64 token-tiles x 8 k-splits) x 4 warps => 3.5 GEMM
// warps/SMSP saturate the fma pipe while 1024 fill blocks stream zeros.
// ============================================================================
__global__ __launch_bounds__(ATPB) void router_kernel(
    const float* __restrict__ x,   // (NTOK, DDIM)
    const float* __restrict__ w,   // (NEXP, DDIM)
    float* __restrict__ out)
{
    const int tid = threadIdx.x;
    const int bid = blockIdx.x;
    const int g   = bid / 3;
    const int r   = bid - 3 * g;

    // ---------------- zero-fill blocks (r == 0,1) ----------------
    if (r != 2) {
        const int fidx = g * 2 + r;                    // 0..1023
        float4* o4 = reinterpret_cast<float4*>(out);
        const float4 z = make_float4(0.f, 0.f, 0.f, 0.f);
        unsigned i = (unsigned)fidx * ATPB + (unsigned)tid;
        const unsigned stride = ZTHREADS;
#pragma unroll 4
        for (int it = 0; it < ZITERS; ++it) {
            __stcs(o4 + i, z);
            i += stride;
        }
        return;
    }

    // ---------------- GEMM blocks: 128 tok x 64 exp x 512 k ----------------
    __shared__ __align__(16) float xs[2][KSTAGE][TOKTILE];   // 16 KB
    __shared__ __align__(16) float ws[2][KSTAGE][68];        // 8.5 KB

    const int split = g & (KSPLIT - 1);
    const int tok0  = (g >> 3) * TOKTILE;
    const int ks    = split * KC;

    const int ex = tid & 7;  const int e0 = ex * 8;
    const int ty = tid >> 3; const int t0 = ty * 8;
    const int e0p = e0 + ((e0 >> 5) << 2);   // bank-swizzled w column

    const float* xg = x + (size_t)(tok0 + tid) * DDIM + ks;   // token row = tid
    const int we = tid & 63; const int wh = tid >> 6;         // expert, k-half
    const float* wg = w + (size_t)we * DDIM + ks + wh * 8;
    const int wep = we + ((we >> 5) << 2);

    unsigned long long acc[4][8];
#pragma unroll
    for (int i = 0; i < 4; i++)
#pragma unroll
        for (int j = 0; j < 8; j++) acc[i][j] = 0ull;

    float4 xr[4], wr[2];

    // prologue: stage 0
#pragma unroll
    for (int j = 0; j < 4; j++) xr[j] = __ldcs((const float4*)(xg + j * 4));
#pragma unroll
    for (int j = 0; j < 2; j++) wr[j] = *(const float4*)(wg + j * 4);
#pragma unroll
    for (int j = 0; j < 4; j++) {
        xs[0][j * 4 + 0][tid] = xr[j].x; xs[0][j * 4 + 1][tid] = xr[j].y;
        xs[0][j * 4 + 2][tid] = xr[j].z; xs[0][j * 4 + 3][tid] = xr[j].w;
    }
#pragma unroll
    for (int j = 0; j < 2; j++) {
        const int kb = wh * 8 + j * 4;
        ws[0][kb + 0][wep] = wr[j].x; ws[0][kb + 1][wep] = wr[j].y;
        ws[0][kb + 2][wep] = wr[j].z; ws[0][kb + 3][wep] = wr[j].w;
    }
    __syncthreads();

    for (int s = 0; s < NSTAGE; s++) {
        const int b = s & 1;
        if (s + 1 < NSTAGE) {
            const int ko = (s + 1) * KSTAGE;
#pragma unroll
            for (int j = 0; j < 4; j++)
                xr[j] = __ldcs((const float4*)(xg + ko + j * 4));
#pragma unroll
            for (int j = 0; j < 2; j++)
                wr[j] = *(const float4*)(wg + ko + j * 4);
        }

#pragma unroll
        for (int k = 0; k < KSTAGE; k++) {
            const ulonglong2 A01 = *(const ulonglong2*)&xs[b][k][t0];
            const ulonglong2 A23 = *(const ulonglong2*)&xs[b][k][t0 + 4];
            const float4 w0 = *(const float4*)&ws[b][k][e0p];
            const float4 w1 = *(const float4*)&ws[b][k][e0p + 4];
            unsigned long long bd[8];
            bd[0] = dup64(w0.x); bd[1] = dup64(w0.y);
            bd[2] = dup64(w0.z); bd[3] = dup64(w0.w);
            bd[4] = dup64(w1.x); bd[5] = dup64(w1.y);
            bd[6] = dup64(w1.z); bd[7] = dup64(w1.w);
            const unsigned long long A[4] = {A01.x, A01.y, A23.x, A23.y};
#pragma unroll
            for (int tp = 0; tp < 4; tp++)
#pragma unroll
                for (int e = 0; e < 8; e++)
                    asm("fma.rn.f32x2 %0, %1, %2, %0;"
                        : "+l"(acc[tp][e]) : "l"(A[tp]), "l"(bd[e]));
        }

        __syncthreads();
        if (s + 1 < NSTAGE) {
            const int nb = (s + 1) & 1;
#pragma unroll
            for (int j = 0; j < 4; j++) {
                xs[nb][j * 4 + 0][tid] = xr[j].x; xs[nb][j * 4 + 1][tid] = xr[j].y;
                xs[nb][j * 4 + 2][tid] = xr[j].z; xs[nb][j * 4 + 3][tid] = xr[j].w;
            }
#pragma unroll
            for (int j = 0; j < 2; j++) {
                const int kb = wh * 8 + j * 4;
                ws[nb][kb + 0][wep] = wr[j].x; ws[nb][kb + 1][wep] = wr[j].y;
                ws[nb][kb + 2][wep] = wr[j].z; ws[nb][kb + 3][wep] = wr[j].w;
            }
            __syncthreads();
        }
    }

    // epilogue: write partial logits
#pragma unroll
    for (int tp = 0; tp < 4; tp++) {
        const int tok = tok0 + t0 + 2 * tp;
        float* p0 = &g_part[split][tok][e0];
        float* p1 = &g_part[split][tok + 1][e0];
#pragma unroll
        for (int e = 0; e < 8; e++) {
            unsigned lo, hi;
            asm("mov.b64 {%0, %1}, %2;" : "=r"(lo), "=r"(hi) : "l"(acc[tp][e]));
            p0[e] = __uint_as_float(lo);
            p1[e] = __uint_as_float(hi);
        }
    }
}

// ============================================================================
// Kernel A2: reduce k-split partials -> softmax + top-2 + probs + g_top
// One warp per token.
// ============================================================================
__global__ __launch_bounds__(TPB) void softmax_kernel(float* __restrict__ out)
{
    const int lane = threadIdx.x & 31;
    const int warp = threadIdx.x >> 5;
    const int tok = blockIdx.x * 8 + warp;

    float v0 = 0.f, v1 = 0.f;
#pragma unroll
    for (int s = 0; s < KSPLIT; s++) {
        v0 += g_part[s][tok][lane];
        v1 += g_part[s][tok][lane + 32];
    }
    const int i0 = lane, i1 = lane + 32;

    float b1v, b2v; int b1i, b2i;
    if (v0 >= v1) { b1v = v0; b1i = i0; b2v = v1; b2i = i1; }
    else          { b1v = v1; b1i = i1; b2v = v0; b2i = i0; }
#pragma unroll
    for (int off = 16; off; off >>= 1) {
        const float o1v = __shfl_xor_sync(0xffffffffu, b1v, off);
        const int   o1i = __shfl_xor_sync(0xffffffffu, b1i, off);
        const float o2v = __shfl_xor_sync(0xffffffffu, b2v, off);
        const int   o2i = __shfl_xor_sync(0xffffffffu, b2i, off);
        const bool o1_better = (o1v > b1v) || (o1v == b1v && o1i < b1i);
        if (o1_better) {
            const bool b1_vs_o2 = (b1v > o2v) || (b1v == o2v && b1i < o2i);
            b2v = b1_vs_o2 ? b1v : o2v;
            b2i = b1_vs_o2 ? b1i : o2i;
            b1v = o1v; b1i = o1i;
        } else {
            const bool o1_vs_b2 = (o1v > b2v) || (o1v == b2v && o1i < b2i);
            if (o1_vs_b2) { b2v = o1v; b2i = o1i; }
        }
    }

    const float m = b1v;
    const float p0 = expf(v0 - m);
    const float p1 = expf(v1 - m);
    float ssum = p0 + p1;
#pragma unroll
    for (int off = 16; off; off >>= 1)
        ssum += __shfl_xor_sync(0xffffffffu, ssum, off);
    const float inv = 1.0f / ssum;

    out[PROBS_OFF + (size_t)tok * NEXP + lane]      = p0 * inv;
    out[PROBS_OFF + (size_t)tok * NEXP + lane + 32] = p1 * inv;

    if (lane == 0) {
        const float e2 = expf(b2v - b1v);
        const float wn = 1.0f / (1.0f + e2);   // normalized top-1 weight
        g_top_e[2 * tok]     = b1i;
        g_top_e[2 * tok + 1] = b2i;
        g_top_v[2 * tok]     = wn;
        g_top_v[2 * tok + 1] = e2 * wn;
    }
}

// ============================================================================
// Kernel B: one block per expert. Ordered exclusive prefix over the flattened
// assignment stream -> slot per assignment; also count[e] * mean(probs[:,e]).
// ============================================================================
__global__ __launch_bounds__(TPB) void slots_kernel(const float* __restrict__ out)
{
    const int e = blockIdx.x;
    const int tid = threadIdx.x;
    const int lane = tid & 31;
    const int warp = tid >> 5;

    __shared__ int wcnt[8];
    int base = 0;
    for (int i0 = 0; i0 < NTOK * 2; i0 += TPB) {
        const int i = i0 + tid;
        const int flag = (g_top_e[i] == e) ? 1 : 0;
        const unsigned m = __ballot_sync(0xffffffffu, flag);
        if (lane == 0) wcnt[warp] = __popc(m);
        __syncthreads();
        int woff = 0, tot = 0;
#pragma unroll
        for (int ww = 0; ww < 8; ww++) {
            const int c = wcnt[ww];
            if (ww < warp) woff += c;
            tot += c;
        }
        if (flag)
            g_slot[i] = base + woff + __popc(m & ((1u << lane) - 1u));
        base += tot;
        __syncthreads();
    }

    float ps = 0.f;
    const float* probs = out + PROBS_OFF;
    for (int n = tid; n < NTOK; n += TPB) ps += probs[(size_t)n * NEXP + e];
    __shared__ float red[TPB];
    red[tid] = ps;
    __syncthreads();
    for (int s = TPB / 2; s; s >>= 1) {
        if (tid < s) red[tid] += red[tid + s];
        __syncthreads();
    }
    if (tid == 0)
        g_floss[e] = ((float)base * (1.0f / (NTOK * 2))) * (red[0] * (1.0f / NTOK));
}

// ============================================================================
// Kernel C: scatter the 16384 nonzeros into dispatch/combine + write loss.
// ============================================================================
__global__ __launch_bounds__(TPB) void scatter_kernel(float* __restrict__ out)
{
    const int i = blockIdx.x * TPB + threadIdx.x;   // exactly NTOK*2 threads
    const int e = g_top_e[i];
    const int s = g_slot[i];
    if (s < CAP) {
        const int tok = i >> 1;
        const size_t idx = (size_t)tok * EC + (size_t)e * CAP + s;
        out[DISP_OFF + idx] = 1.0f;
        out[COMB_OFF + idx] = g_top_v[i];
    }
    if (blockIdx.x == 0 && threadIdx.x == 0) {
        float ssum = 0.f;
        for (int ee = 0; ee < NEXP; ee++) ssum += g_floss[ee];
        out[LOSS_OFF] = 0.01f * (float)NEXP * ssum;
    }
}

// ============================================================================
extern "C" void kernel_launch(void* const* d_in, const int* in_sizes, int n_in,
                              void* d_out, int out_size)
{
    (void)in_sizes; (void)n_in; (void)out_size;
    const float* x = (const float*)d_in[0];
    const float* w = (const float*)d_in[1];
    float* out = (float*)d_out;

    router_kernel<<<GRID, ATPB>>>(x, w, out);
    softmax_kernel<<<NTOK / 8, TPB>>>(out);
    slots_kernel<<<NEXP, TPB>>>(out);
    scatter_kernel<<<(NTOK * 2) / TPB, TPB>>>(out);
}

// round 11
// speedup vs baseline: 1.2362x; 1.0473x over previous
#include <cuda_runtime.h>
#include <cstdint>

// ---------------- problem constants ----------------
#define NTOK 8192
#define DDIM 4096
#define NEXP 64
#define CAP  160
#define EC   (NEXP * CAP)                 // 10240
#define DISP_OFF  ((size_t)0)
#define COMB_OFF  ((size_t)NTOK * EC)                  // 83,886,080
#define PROBS_OFF ((size_t)2 * NTOK * EC)              // 167,772,160
#define LOSS_OFF  (PROBS_OFF + (size_t)NTOK * NEXP)    // 168,296,448

#define KSPLIT 8
#define KC     (DDIM / KSPLIT)            // 512
#define KSTAGE 16
#define NSTAGE (KC / KSTAGE)              // 32
#define TOKTILE 128
#define NTILE  (NTOK / TOKTILE)           // 64
#define GEMM_BLOCKS (NTILE * KSPLIT)      // 512
#define ZERO_BLOCKS 1024
#define GRID (GEMM_BLOCKS + ZERO_BLOCKS)  // 1536
#define ATPB 128
#define TPB  256

#define SMBLOCKS (NTOK / 8)               // 1024 softmax blocks

// zero-fill geometry
#define ZTHREADS (ZERO_BLOCKS * ATPB)             // 131072
#define TOTAL4   (PROBS_OFF / 4)                  // 41,943,040 float4
#define ZITERS   (TOTAL4 / ZTHREADS)              // 320 exactly

// ---------------- scratch ----------------
__device__ float g_part[KSPLIT][NTOK][NEXP];   // 16 MB partial logits
__device__ int   g_top_e[NTOK * 2];
__device__ float g_top_v[NTOK * 2];
__device__ float g_psum[SMBLOCKS][NEXP];       // per-softmax-block probs sums
__device__ float g_floss[NEXP];
__device__ int   g_done;                       // finalize arrival (self-resetting)

__device__ __forceinline__ unsigned long long dup64(float v) {
    unsigned long long r;
    asm("mov.b64 %0, {%1, %1};" : "=l"(r) : "f"(v));
    return r;
}

// ============================================================================
// Kernel A: fused [zero-fill] + [k-split GEMM], interleaved block mapping
// (every 3rd block is a GEMM block). 512 GEMM blocks x 4 warps saturate the
// fma pipe while 1024 fill blocks stream zeros at the DRAM write ceiling.
// ============================================================================
__global__ __launch_bounds__(ATPB) void router_kernel(
    const float* __restrict__ x,   // (NTOK, DDIM)
    const float* __restrict__ w,   // (NEXP, DDIM)
    float* __restrict__ out)
{
    const int tid = threadIdx.x;
    const int bid = blockIdx.x;
    const int g   = bid / 3;
    const int r   = bid - 3 * g;

    // ---------------- zero-fill blocks (r == 0,1) ----------------
    if (r != 2) {
        const int fidx = g * 2 + r;                    // 0..1023
        float4* o4 = reinterpret_cast<float4*>(out);
        const float4 z = make_float4(0.f, 0.f, 0.f, 0.f);
        unsigned i = (unsigned)fidx * ATPB + (unsigned)tid;
        const unsigned stride = ZTHREADS;
#pragma unroll 4
        for (int it = 0; it < ZITERS; ++it) {
            __stcs(o4 + i, z);
            i += stride;
        }
        return;
    }

    // ---------------- GEMM blocks: 128 tok x 64 exp x 512 k ----------------
    __shared__ __align__(16) float xs[2][KSTAGE][TOKTILE];   // 16 KB
    __shared__ __align__(16) float ws[2][KSTAGE][68];        // 8.5 KB

    const int split = g & (KSPLIT - 1);
    const int tok0  = (g >> 3) * TOKTILE;
    const int ks    = split * KC;

    const int ex = tid & 7;  const int e0 = ex * 8;
    const int ty = tid >> 3; const int t0 = ty * 8;
    const int e0p = e0 + ((e0 >> 5) << 2);   // bank-swizzled w column

    const float* xg = x + (size_t)(tok0 + tid) * DDIM + ks;   // token row = tid
    const int we = tid & 63; const int wh = tid >> 6;         // expert, k-half
    const float* wg = w + (size_t)we * DDIM + ks + wh * 8;
    const int wep = we + ((we >> 5) << 2);

    unsigned long long acc[4][8];
#pragma unroll
    for (int i = 0; i < 4; i++)
#pragma unroll
        for (int j = 0; j < 8; j++) acc[i][j] = 0ull;

    float4 xr[4], wr[2];

    // prologue: stage 0
#pragma unroll
    for (int j = 0; j < 4; j++) xr[j] = __ldcs((const float4*)(xg + j * 4));
#pragma unroll
    for (int j = 0; j < 2; j++) wr[j] = *(const float4*)(wg + j * 4);
#pragma unroll
    for (int j = 0; j < 4; j++) {
        xs[0][j * 4 + 0][tid] = xr[j].x; xs[0][j * 4 + 1][tid] = xr[j].y;
        xs[0][j * 4 + 2][tid] = xr[j].z; xs[0][j * 4 + 3][tid] = xr[j].w;
    }
#pragma unroll
    for (int j = 0; j < 2; j++) {
        const int kb = wh * 8 + j * 4;
        ws[0][kb + 0][wep] = wr[j].x; ws[0][kb + 1][wep] = wr[j].y;
        ws[0][kb + 2][wep] = wr[j].z; ws[0][kb + 3][wep] = wr[j].w;
    }
    __syncthreads();

    for (int s = 0; s < NSTAGE; s++) {
        const int b = s & 1;
        if (s + 1 < NSTAGE) {
            const int ko = (s + 1) * KSTAGE;
#pragma unroll
            for (int j = 0; j < 4; j++)
                xr[j] = __ldcs((const float4*)(xg + ko + j * 4));
#pragma unroll
            for (int j = 0; j < 2; j++)
                wr[j] = *(const float4*)(wg + ko + j * 4);
        }

#pragma unroll
        for (int k = 0; k < KSTAGE; k++) {
            const ulonglong2 A01 = *(const ulonglong2*)&xs[b][k][t0];
            const ulonglong2 A23 = *(const ulonglong2*)&xs[b][k][t0 + 4];
            const float4 w0 = *(const float4*)&ws[b][k][e0p];
            const float4 w1 = *(const float4*)&ws[b][k][e0p + 4];
            unsigned long long bd[8];
            bd[0] = dup64(w0.x); bd[1] = dup64(w0.y);
            bd[2] = dup64(w0.z); bd[3] = dup64(w0.w);
            bd[4] = dup64(w1.x); bd[5] = dup64(w1.y);
            bd[6] = dup64(w1.z); bd[7] = dup64(w1.w);
            const unsigned long long A[4] = {A01.x, A01.y, A23.x, A23.y};
#pragma unroll
            for (int tp = 0; tp < 4; tp++)
#pragma unroll
                for (int e = 0; e < 8; e++)
                    asm("fma.rn.f32x2 %0, %1, %2, %0;"
                        : "+l"(acc[tp][e]) : "l"(A[tp]), "l"(bd[e]));
        }

        __syncthreads();
        if (s + 1 < NSTAGE) {
            const int nb = (s + 1) & 1;
#pragma unroll
            for (int j = 0; j < 4; j++) {
                xs[nb][j * 4 + 0][tid] = xr[j].x; xs[nb][j * 4 + 1][tid] = xr[j].y;
                xs[nb][j * 4 + 2][tid] = xr[j].z; xs[nb][j * 4 + 3][tid] = xr[j].w;
            }
#pragma unroll
            for (int j = 0; j < 2; j++) {
                const int kb = wh * 8 + j * 4;
                ws[nb][kb + 0][wep] = wr[j].x; ws[nb][kb + 1][wep] = wr[j].y;
                ws[nb][kb + 2][wep] = wr[j].z; ws[nb][kb + 3][wep] = wr[j].w;
            }
            __syncthreads();
        }
    }

    // epilogue: write partial logits
#pragma unroll
    for (int tp = 0; tp < 4; tp++) {
        const int tok = tok0 + t0 + 2 * tp;
        float* p0 = &g_part[split][tok][e0];
        float* p1 = &g_part[split][tok + 1][e0];
#pragma unroll
        for (int e = 0; e < 8; e++) {
            unsigned lo, hi;
            asm("mov.b64 {%0, %1}, %2;" : "=r"(lo), "=r"(hi) : "l"(acc[tp][e]));
            p0[e] = __uint_as_float(lo);
            p1[e] = __uint_as_float(hi);
        }
    }
}

// ============================================================================
// Kernel A2: reduce k-split partials -> softmax + top-2 + probs + g_top.
// One warp per token (8 tokens/block). Also emits per-block per-expert
// probability partial sums (fixed-order) for the aux loss.
// ============================================================================
__global__ __launch_bounds__(TPB) void softmax_kernel(float* __restrict__ out)
{
    const int lane = threadIdx.x & 31;
    const int warp = threadIdx.x >> 5;
    const int tok = blockIdx.x * 8 + warp;

    __shared__ float pb[8][64];

    float v0 = 0.f, v1 = 0.f;
#pragma unroll
    for (int s = 0; s < KSPLIT; s++) {
        v0 += g_part[s][tok][lane];
        v1 += g_part[s][tok][lane + 32];
    }
    const int i0 = lane, i1 = lane + 32;

    float b1v, b2v; int b1i, b2i;
    if (v0 >= v1) { b1v = v0; b1i = i0; b2v = v1; b2i = i1; }
    else          { b1v = v1; b1i = i1; b2v = v0; b2i = i0; }
#pragma unroll
    for (int off = 16; off; off >>= 1) {
        const float o1v = __shfl_xor_sync(0xffffffffu, b1v, off);
        const int   o1i = __shfl_xor_sync(0xffffffffu, b1i, off);
        const float o2v = __shfl_xor_sync(0xffffffffu, b2v, off);
        const int   o2i = __shfl_xor_sync(0xffffffffu, b2i, off);
        const bool o1_better = (o1v > b1v) || (o1v == b1v && o1i < b1i);
        if (o1_better) {
            const bool b1_vs_o2 = (b1v > o2v) || (b1v == o2v && b1i < o2i);
            b2v = b1_vs_o2 ? b1v : o2v;
            b2i = b1_vs_o2 ? b1i : o2i;
            b1v = o1v; b1i = o1i;
        } else {
            const bool o1_vs_b2 = (o1v > b2v) || (o1v == b2v && o1i < b2i);
            if (o1_vs_b2) { b2v = o1v; b2i = o1i; }
        }
    }

    const float m = b1v;
    const float p0 = expf(v0 - m);
    const float p1 = expf(v1 - m);
    float ssum = p0 + p1;
#pragma unroll
    for (int off = 16; off; off >>= 1)
        ssum += __shfl_xor_sync(0xffffffffu, ssum, off);
    const float inv = 1.0f / ssum;

    const float q0 = p0 * inv;
    const float q1 = p1 * inv;
    out[PROBS_OFF + (size_t)tok * NEXP + lane]      = q0;
    out[PROBS_OFF + (size_t)tok * NEXP + lane + 32] = q1;
    pb[warp][lane]      = q0;
    pb[warp][lane + 32] = q1;

    if (lane == 0) {
        const float e2 = expf(b2v - b1v);
        const float wn = 1.0f / (1.0f + e2);   // normalized top-1 weight
        g_top_e[2 * tok]     = b1i;
        g_top_e[2 * tok + 1] = b2i;
        g_top_v[2 * tok]     = wn;
        g_top_v[2 * tok + 1] = e2 * wn;
    }

    __syncthreads();
    // per-block expert partial sums, fixed order over the 8 tokens
    if (threadIdx.x < 64) {
        float s = 0.f;
#pragma unroll
        for (int t = 0; t < 8; t++) s += pb[t][threadIdx.x];
        g_psum[blockIdx.x][threadIdx.x] = s;
    }
}

// ============================================================================
// Kernel B: one block per expert. Two-pass strip scan (2 barriers total):
// each warp counts its contiguous 2048-entry strip, exclusive base across
// warps, then re-scan assigning slots in flattened order + inline scatter.
// Also reduces probs partials and the fused aux loss.
// ============================================================================
__global__ __launch_bounds__(TPB) void finalize_kernel(float* __restrict__ out)
{
    const int e = blockIdx.x;
    const int tid = threadIdx.x;
    const int lane = tid & 31;
    const int warp = tid >> 5;

    __shared__ int wcnt[8];
    __shared__ float red[TPB];

    // pass 1: per-warp strip counts (strip = 2048 consecutive assignments)
    const int strip0 = warp * 2048;
    int cnt = 0;
#pragma unroll 4
    for (int j = lane; j < 2048; j += 32)
        cnt += (g_top_e[strip0 + j] == e) ? 1 : 0;
#pragma unroll
    for (int off = 16; off; off >>= 1)
        cnt += __shfl_xor_sync(0xffffffffu, cnt, off);
    if (lane == 0) wcnt[warp] = cnt;
    __syncthreads();

    int base = 0, tot = 0;
#pragma unroll
    for (int ww = 0; ww < 8; ww++) {
        const int c = wcnt[ww];
        if (ww < warp) base += c;
        tot += c;
    }

    // pass 2: assign slots in flattened order + inline scatter
    int run = base;
    for (int j0 = 0; j0 < 2048; j0 += 32) {
        const int i = strip0 + j0 + lane;
        const int flag = (g_top_e[i] == e) ? 1 : 0;
        const unsigned m = __ballot_sync(0xffffffffu, flag);
        if (flag) {
            const int slot = run + __popc(m & ((1u << lane) - 1u));
            if (slot < CAP) {
                const int tok = i >> 1;
                const size_t idx = (size_t)tok * EC + (size_t)e * CAP + slot;
                out[DISP_OFF + idx] = 1.0f;
                out[COMB_OFF + idx] = g_top_v[i];
            }
        }
        run += __popc(m);
    }

    // probs column-e sum from per-block partials (fixed-order tree)
    float ps = 0.f;
#pragma unroll
    for (int b = tid; b < SMBLOCKS; b += TPB) ps += g_psum[b][e];
    red[tid] = ps;
    __syncthreads();
    for (int s = TPB / 2; s; s >>= 1) {
        if (tid < s) red[tid] += red[tid + s];
        __syncthreads();
    }

    if (tid == 0) {
        g_floss[e] = ((float)tot * (1.0f / (NTOK * 2))) * (red[0] * (1.0f / NTOK));
        __threadfence();
        if (atomicAdd(&g_done, 1) == NEXP - 1) {
            __threadfence();
            float ssum = 0.f;
            for (int ee = 0; ee < NEXP; ee++) ssum += g_floss[ee];
            out[LOSS_OFF] = 0.01f * (float)NEXP * ssum;
            g_done = 0;                      // self-reset for graph replay
        }
    }
}

// ============================================================================
extern "C" void kernel_launch(void* const* d_in, const int* in_sizes, int n_in,
                              void* d_out, int out_size)
{
    (void)in_sizes; (void)n_in; (void)out_size;
    const float* x = (const float*)d_in[0];
    const float* w = (const float*)d_in[1];
    float* out = (float*)d_out;

    router_kernel<<<GRID, ATPB>>>(x, w, out);
    softmax_kernel<<<SMBLOCKS, TPB>>>(out);
    finalize_kernel<<<NEXP, TPB>>>(out);
}